// round 1
// baseline (speedup 1.0000x reference)
#include <cuda_runtime.h>
#include <math.h>

#define TT 64
#define DM 16
#define DFF 32
#define EPSF 1e-5f

__global__ __launch_bounds__(128, 3)
void block_kernel(const float* __restrict__ x,
                  const float* __restrict__ Wk, const float* __restrict__ Wq,
                  const float* __restrict__ Wv,
                  const float* __restrict__ ln1g, const float* __restrict__ ln1b,
                  const float* __restrict__ ln2g, const float* __restrict__ ln2b,
                  const float* __restrict__ W1, const float* __restrict__ b1,
                  const float* __restrict__ W2, const float* __restrict__ b2,
                  float* __restrict__ out)
{
    __shared__ float sWk[DM][DM], sWq[DM][DM], sWv[DM][DM];
    __shared__ float sW1[DM][DFF], sW2[DFF][DM];
    __shared__ float sb1[DFF], sb2[DM], sg1[DM], sB1[DM], sg2[DM], sB2[DM];
    __shared__ float sK[2][TT][DM], sV[2][TT][DM];

    const int tid  = threadIdx.x;
    const int half = tid >> 6;        // which batch element within this CTA
    const int t    = tid & 63;        // token index
    const long long b = (long long)blockIdx.x * 2 + half;

    // ---- cooperative weight load into smem ----
    for (int i = tid; i < DM * DM; i += 128) {
        ((float*)sWk)[i] = Wk[i];
        ((float*)sWq)[i] = Wq[i];
        ((float*)sWv)[i] = Wv[i];
    }
    for (int i = tid; i < DM * DFF; i += 128) {
        ((float*)sW1)[i] = W1[i];
        ((float*)sW2)[i] = W2[i];
    }
    if (tid < DFF) sb1[tid] = b1[tid];
    if (tid < DM) {
        sb2[tid] = b2[tid];
        sg1[tid] = ln1g[tid]; sB1[tid] = ln1b[tid];
        sg2[tid] = ln2g[tid]; sB2[tid] = ln2b[tid];
    }

    // ---- load this token's row (coalesced float4) ----
    float xr[DM];
    const float* xp = x + (b * TT + t) * DM;
    #pragma unroll
    for (int c = 0; c < DM; c += 4) {
        float4 v4 = *reinterpret_cast<const float4*>(xp + c);
        xr[c] = v4.x; xr[c + 1] = v4.y; xr[c + 2] = v4.z; xr[c + 3] = v4.w;
    }
    __syncthreads();   // weights ready

    // ---- LayerNorm 1 ----
    float mu = 0.f;
    #pragma unroll
    for (int c = 0; c < DM; c++) mu += xr[c];
    mu *= (1.0f / DM);
    float var = 0.f;
    #pragma unroll
    for (int c = 0; c < DM; c++) { float d = xr[c] - mu; var = fmaf(d, d, var); }
    var *= (1.0f / DM);
    float rstd = rsqrtf(var + EPSF);
    float h[DM];
    #pragma unroll
    for (int c = 0; c < DM; c++) h[c] = (xr[c] - mu) * rstd * sg1[c] + sB1[c];

    // ---- Q, K, V projections (weights broadcast from smem) ----
    float q[DM], kk[DM], vv[DM];
    #pragma unroll
    for (int j = 0; j < DM; j++) { q[j] = 0.f; kk[j] = 0.f; vv[j] = 0.f; }
    #pragma unroll
    for (int c = 0; c < DM; c++) {
        float hc = h[c];
        #pragma unroll
        for (int j = 0; j < DM; j++) {
            q[j]  = fmaf(hc, sWq[c][j], q[j]);
            kk[j] = fmaf(hc, sWk[c][j], kk[j]);
            vv[j] = fmaf(hc, sWv[c][j], vv[j]);
        }
    }
    #pragma unroll
    for (int c = 0; c < DM; c += 4) {
        *reinterpret_cast<float4*>(&sK[half][t][c]) = make_float4(kk[c], kk[c+1], kk[c+2], kk[c+3]);
        *reinterpret_cast<float4*>(&sV[half][t][c]) = make_float4(vv[c], vv[c+1], vv[c+2], vv[c+3]);
    }
    __syncthreads();   // K/V tiles ready

    // ---- causal attention: scores in registers, warp-uniform trip bound ----
    const int whi = t | 31;          // all 32 tokens of a warp share this bound
    float sc[TT];
    float m = -3.0e38f;
    #pragma unroll
    for (int s = 0; s < TT; s++) {
        if (s > whi) break;
        float d0 = 0.f;
        #pragma unroll
        for (int c = 0; c < DM; c++) d0 = fmaf(q[c], sK[half][s][c], d0);
        float scv = (s <= t) ? d0 * 0.25f : -3.0e38f;   // 1/sqrt(16) = 0.25
        sc[s] = scv;
        m = fmaxf(m, scv);
    }
    float l = 0.f;
    #pragma unroll
    for (int s = 0; s < TT; s++) {
        if (s > whi) break;
        float p = __expf(sc[s] - m);
        sc[s] = p;
        l += p;
    }
    float inv = __fdividef(1.0f, l);
    float y[DM];
    #pragma unroll
    for (int c = 0; c < DM; c++) y[c] = 0.f;
    #pragma unroll
    for (int s = 0; s < TT; s++) {
        if (s > whi) break;
        float p = sc[s];
        #pragma unroll
        for (int c = 0; c < DM; c++) y[c] = fmaf(p, sV[half][s][c], y[c]);
    }
    #pragma unroll
    for (int c = 0; c < DM; c++) xr[c] = fmaf(y[c], inv, xr[c]);   // residual 1

    // ---- LayerNorm 2 ----
    mu = 0.f;
    #pragma unroll
    for (int c = 0; c < DM; c++) mu += xr[c];
    mu *= (1.0f / DM);
    var = 0.f;
    #pragma unroll
    for (int c = 0; c < DM; c++) { float d = xr[c] - mu; var = fmaf(d, d, var); }
    var *= (1.0f / DM);
    rstd = rsqrtf(var + EPSF);
    float h2[DM];
    #pragma unroll
    for (int c = 0; c < DM; c++) h2[c] = (xr[c] - mu) * rstd * sg2[c] + sB2[c];

    // ---- FFN: h2 @ W1 + b1 -> exact GELU -> @ W2 + b2, residual ----
    float f[DFF];
    #pragma unroll
    for (int j = 0; j < DFF; j++) f[j] = sb1[j];
    #pragma unroll
    for (int c = 0; c < DM; c++) {
        float hc = h2[c];
        #pragma unroll
        for (int j = 0; j < DFF; j++) f[j] = fmaf(hc, sW1[c][j], f[j]);
    }
    #pragma unroll
    for (int j = 0; j < DFF; j++) {
        float u = f[j];
        f[j] = 0.5f * u * (1.0f + erff(u * 0.70710678118654752f));
    }
    float o[DM];
    #pragma unroll
    for (int c = 0; c < DM; c++) o[c] = xr[c] + sb2[c];
    #pragma unroll
    for (int j = 0; j < DFF; j++) {
        float fj = f[j];
        #pragma unroll
        for (int c = 0; c < DM; c++) o[c] = fmaf(fj, sW2[j][c], o[c]);
    }

    // ---- store (coalesced float4) ----
    float* op = out + (b * TT + t) * DM;
    #pragma unroll
    for (int c = 0; c < DM; c += 4) {
        *reinterpret_cast<float4*>(op + c) = make_float4(o[c], o[c+1], o[c+2], o[c+3]);
    }
}

extern "C" void kernel_launch(void* const* d_in, const int* in_sizes, int n_in,
                              void* d_out, int out_size)
{
    const float* x    = (const float*)d_in[0];
    const float* Wk   = (const float*)d_in[1];
    const float* Wq   = (const float*)d_in[2];
    const float* Wv   = (const float*)d_in[3];
    const float* ln1g = (const float*)d_in[4];
    const float* ln1b = (const float*)d_in[5];
    const float* ln2g = (const float*)d_in[6];
    const float* ln2b = (const float*)d_in[7];
    const float* W1   = (const float*)d_in[8];
    const float* b1   = (const float*)d_in[9];
    const float* W2   = (const float*)d_in[10];
    const float* b2   = (const float*)d_in[11];
    float* out = (float*)d_out;

    int B = in_sizes[0] / (TT * DM);      // 16384
    dim3 grid((B + 1) / 2);               // 2 batch elements per CTA
    block_kernel<<<grid, 128>>>(x, Wk, Wq, Wv, ln1g, ln1b, ln2g, ln2b,
                                W1, b1, W2, b2, out);
}

// round 2
// speedup vs baseline: 1.2396x; 1.2396x over previous
#include <cuda_runtime.h>
#include <math.h>

#define TT 64
#define DM 16
#define DFF 32
#define EPSF 1e-5f

typedef unsigned long long u64;

__device__ __forceinline__ u64 pk2(float lo, float hi) {
    u64 r; asm("mov.b64 %0,{%1,%2};" : "=l"(r) : "f"(lo), "f"(hi)); return r;
}
__device__ __forceinline__ float2 up2(u64 v) {
    float2 f; asm("mov.b64 {%0,%1},%2;" : "=f"(f.x), "=f"(f.y) : "l"(v)); return f;
}
__device__ __forceinline__ u64 f2fma(u64 a, u64 b, u64 c) {
    u64 d; asm("fma.rn.f32x2 %0,%1,%2,%3;" : "=l"(d) : "l"(a), "l"(b), "l"(c)); return d;
}
__device__ __forceinline__ u64 f2add(u64 a, u64 b) {
    u64 d; asm("add.rn.f32x2 %0,%1,%2;" : "=l"(d) : "l"(a), "l"(b)); return d;
}
__device__ __forceinline__ u64 f2mul(u64 a, u64 b) {
    u64 d; asm("mul.rn.f32x2 %0,%1,%2;" : "=l"(d) : "l"(a), "l"(b)); return d;
}
// load 4 consecutive floats from smem as one LDS.128, return as two packed pairs
__device__ __forceinline__ void ld2(const float* p, u64& a, u64& b) {
    float4 v = *reinterpret_cast<const float4*>(p);
    a = pk2(v.x, v.y); b = pk2(v.z, v.w);
}

__global__ __launch_bounds__(128, 3)
void block_kernel(const float* __restrict__ x,
                  const float* __restrict__ Wk, const float* __restrict__ Wq,
                  const float* __restrict__ Wv,
                  const float* __restrict__ ln1g, const float* __restrict__ ln1b,
                  const float* __restrict__ ln2g, const float* __restrict__ ln2b,
                  const float* __restrict__ W1, const float* __restrict__ b1,
                  const float* __restrict__ W2, const float* __restrict__ b2,
                  float* __restrict__ out)
{
    __shared__ float sWk[DM][DM], sWq[DM][DM], sWv[DM][DM];
    __shared__ float sW1[DM][DFF], sW2[DFF][DM];
    __shared__ float sb1[DFF], sb2[DM], sg1[DM], sB1[DM], sg2[DM], sB2[DM];
    __shared__ float sK[2][TT][DM], sV[2][TT][DM];

    const int tid  = threadIdx.x;
    const int half = tid >> 6;
    const int t    = tid & 63;
    const long long b = (long long)blockIdx.x * 2 + half;

    // ---- cooperative weight load ----
    for (int i = tid; i < DM * DM; i += 128) {
        ((float*)sWk)[i] = Wk[i];
        ((float*)sWq)[i] = Wq[i];
        ((float*)sWv)[i] = Wv[i];
    }
    for (int i = tid; i < DM * DFF; i += 128) {
        ((float*)sW1)[i] = W1[i];
        ((float*)sW2)[i] = W2[i];
    }
    if (tid < DFF) sb1[tid] = b1[tid];
    if (tid < DM) {
        sb2[tid] = b2[tid];
        sg1[tid] = ln1g[tid]; sB1[tid] = ln1b[tid];
        sg2[tid] = ln2g[tid]; sB2[tid] = ln2b[tid];
    }

    // ---- load token row, packed (8 x f32x2) ----
    u64 xp[8];
    const float* xptr = x + (b * TT + t) * DM;
    #pragma unroll
    for (int i = 0; i < 4; i++) {
        float4 v4 = *reinterpret_cast<const float4*>(xptr + 4 * i);
        xp[2 * i]     = pk2(v4.x, v4.y);
        xp[2 * i + 1] = pk2(v4.z, v4.w);
    }
    __syncthreads();

    // ---- LayerNorm 1 (packed) ----
    u64 acc = f2add(f2add(f2add(xp[0], xp[1]), f2add(xp[2], xp[3])),
                    f2add(f2add(xp[4], xp[5]), f2add(xp[6], xp[7])));
    float2 s2 = up2(acc);
    float mu = (s2.x + s2.y) * (1.0f / DM);
    u64 nmu = pk2(-mu, -mu);
    u64 v0 = 0ull, v1 = 0ull;
    #pragma unroll
    for (int i = 0; i < 8; i += 2) {
        u64 d0 = f2add(xp[i], nmu);     v0 = f2fma(d0, d0, v0);
        u64 d1 = f2add(xp[i + 1], nmu); v1 = f2fma(d1, d1, v1);
    }
    s2 = up2(f2add(v0, v1));
    float rstd = rsqrtf((s2.x + s2.y) * (1.0f / DM) + EPSF);
    u64 rr = pk2(rstd, rstd);

    float hs[DM];              // scalar h for weight-broadcast loops
    #pragma unroll
    for (int i = 0; i < 4; i++) {
        u64 ga, gb, ba, bb;
        ld2(&sg1[4 * i], ga, gb);
        ld2(&sB1[4 * i], ba, bb);
        u64 h0 = f2fma(f2mul(f2add(xp[2 * i], nmu), rr), ga, ba);
        u64 h1 = f2fma(f2mul(f2add(xp[2 * i + 1], nmu), rr), gb, bb);
        float2 a = up2(h0), c = up2(h1);
        hs[4 * i] = a.x; hs[4 * i + 1] = a.y; hs[4 * i + 2] = c.x; hs[4 * i + 3] = c.y;
    }

    // ---- Q,K,V projections (packed accumulators) ----
    u64 qp[8], kp[8], vp[8];
    #pragma unroll
    for (int i = 0; i < 8; i++) { qp[i] = 0ull; kp[i] = 0ull; vp[i] = 0ull; }
    #pragma unroll
    for (int c = 0; c < DM; c++) {
        u64 hb = pk2(hs[c], hs[c]);
        #pragma unroll
        for (int i = 0; i < 4; i++) {
            u64 wa, wb;
            ld2(&sWq[c][4 * i], wa, wb);
            qp[2 * i]     = f2fma(hb, wa, qp[2 * i]);
            qp[2 * i + 1] = f2fma(hb, wb, qp[2 * i + 1]);
            ld2(&sWk[c][4 * i], wa, wb);
            kp[2 * i]     = f2fma(hb, wa, kp[2 * i]);
            kp[2 * i + 1] = f2fma(hb, wb, kp[2 * i + 1]);
            ld2(&sWv[c][4 * i], wa, wb);
            vp[2 * i]     = f2fma(hb, wa, vp[2 * i]);
            vp[2 * i + 1] = f2fma(hb, wb, vp[2 * i + 1]);
        }
    }
    // write K,V tiles (4 x STS.128 each)
    #pragma unroll
    for (int i = 0; i < 4; i++) {
        float2 a = up2(kp[2 * i]), c = up2(kp[2 * i + 1]);
        *reinterpret_cast<float4*>(&sK[half][t][4 * i]) = make_float4(a.x, a.y, c.x, c.y);
        a = up2(vp[2 * i]); c = up2(vp[2 * i + 1]);
        *reinterpret_cast<float4*>(&sV[half][t][4 * i]) = make_float4(a.x, a.y, c.x, c.y);
    }
    // fold 1/sqrt(C)=0.25 into q once
    {
        u64 qtr = pk2(0.25f, 0.25f);
        #pragma unroll
        for (int i = 0; i < 8; i++) qp[i] = f2mul(qp[i], qtr);
    }
    __syncthreads();

    // ---- causal attention, warp-uniform trip bound ----
    const int whi = t | 31;
    float sc[TT];
    float m = -3.0e38f;
    #pragma unroll
    for (int s = 0; s < TT; s++) {
        if (s > whi) break;
        u64 a0 = 0ull, a1 = 0ull;
        const float* kr = &sK[half][s][0];
        #pragma unroll
        for (int i = 0; i < 4; i++) {
            u64 ka, kb;
            ld2(kr + 4 * i, ka, kb);
            a0 = f2fma(qp[2 * i],     ka, a0);
            a1 = f2fma(qp[2 * i + 1], kb, a1);
        }
        float2 f = up2(f2add(a0, a1));
        float d0 = f.x + f.y;
        float scv = (s <= t) ? d0 : -3.0e38f;
        sc[s] = scv;
        m = fmaxf(m, scv);
    }
    float l = 0.f;
    #pragma unroll
    for (int s = 0; s < TT; s++) {
        if (s > whi) break;
        float p = __expf(sc[s] - m);
        sc[s] = p;
        l += p;
    }
    float inv = __fdividef(1.0f, l);

    u64 yp[8];
    #pragma unroll
    for (int i = 0; i < 8; i++) yp[i] = 0ull;
    #pragma unroll
    for (int s = 0; s < TT; s++) {
        if (s > whi) break;
        u64 pp = pk2(sc[s], sc[s]);
        const float* vr = &sV[half][s][0];
        #pragma unroll
        for (int i = 0; i < 4; i++) {
            u64 va, vb;
            ld2(vr + 4 * i, va, vb);
            yp[2 * i]     = f2fma(pp, va, yp[2 * i]);
            yp[2 * i + 1] = f2fma(pp, vb, yp[2 * i + 1]);
        }
    }
    {   // residual 1: x += y * inv
        u64 ip = pk2(inv, inv);
        #pragma unroll
        for (int i = 0; i < 8; i++) xp[i] = f2fma(yp[i], ip, xp[i]);
    }

    // ---- LayerNorm 2 (packed) ----
    acc = f2add(f2add(f2add(xp[0], xp[1]), f2add(xp[2], xp[3])),
                f2add(f2add(xp[4], xp[5]), f2add(xp[6], xp[7])));
    s2 = up2(acc);
    mu = (s2.x + s2.y) * (1.0f / DM);
    nmu = pk2(-mu, -mu);
    v0 = 0ull; v1 = 0ull;
    #pragma unroll
    for (int i = 0; i < 8; i += 2) {
        u64 d0 = f2add(xp[i], nmu);     v0 = f2fma(d0, d0, v0);
        u64 d1 = f2add(xp[i + 1], nmu); v1 = f2fma(d1, d1, v1);
    }
    s2 = up2(f2add(v0, v1));
    rstd = rsqrtf((s2.x + s2.y) * (1.0f / DM) + EPSF);
    rr = pk2(rstd, rstd);
    #pragma unroll
    for (int i = 0; i < 4; i++) {
        u64 ga, gb, ba, bb;
        ld2(&sg2[4 * i], ga, gb);
        ld2(&sB2[4 * i], ba, bb);
        u64 h0 = f2fma(f2mul(f2add(xp[2 * i], nmu), rr), ga, ba);
        u64 h1 = f2fma(f2mul(f2add(xp[2 * i + 1], nmu), rr), gb, bb);
        float2 a = up2(h0), c = up2(h1);
        hs[4 * i] = a.x; hs[4 * i + 1] = a.y; hs[4 * i + 2] = c.x; hs[4 * i + 3] = c.y;
    }

    // ---- FFN1: f = h2 @ W1 + b1 (32 outputs, packed in 16 pairs) ----
    u64 fp[16];
    #pragma unroll
    for (int i = 0; i < 8; i++) ld2(&sb1[4 * i], fp[2 * i], fp[2 * i + 1]);
    #pragma unroll
    for (int c = 0; c < DM; c++) {
        u64 hb = pk2(hs[c], hs[c]);
        #pragma unroll
        for (int i = 0; i < 8; i++) {
            u64 wa, wb;
            ld2(&sW1[c][4 * i], wa, wb);
            fp[2 * i]     = f2fma(hb, wa, fp[2 * i]);
            fp[2 * i + 1] = f2fma(hb, wb, fp[2 * i + 1]);
        }
    }
    // exact GELU per element
    float fs[DFF];
    #pragma unroll
    for (int i = 0; i < 16; i++) {
        float2 f = up2(fp[i]);
        fs[2 * i]     = 0.5f * f.x * (1.0f + erff(f.x * 0.70710678118654752f));
        fs[2 * i + 1] = 0.5f * f.y * (1.0f + erff(f.y * 0.70710678118654752f));
    }

    // ---- FFN2 + residual: out = x + b2 + f @ W2 ----
    u64 op[8];
    #pragma unroll
    for (int i = 0; i < 4; i++) {
        u64 ba, bb;
        ld2(&sb2[4 * i], ba, bb);
        op[2 * i]     = f2add(xp[2 * i], ba);
        op[2 * i + 1] = f2add(xp[2 * i + 1], bb);
    }
    #pragma unroll
    for (int j = 0; j < DFF; j++) {
        u64 fb = pk2(fs[j], fs[j]);
        #pragma unroll
        for (int i = 0; i < 4; i++) {
            u64 wa, wb;
            ld2(&sW2[j][4 * i], wa, wb);
            op[2 * i]     = f2fma(fb, wa, op[2 * i]);
            op[2 * i + 1] = f2fma(fb, wb, op[2 * i + 1]);
        }
    }

    // ---- store ----
    float* optr = out + (b * TT + t) * DM;
    #pragma unroll
    for (int i = 0; i < 4; i++) {
        float2 a = up2(op[2 * i]), c = up2(op[2 * i + 1]);
        *reinterpret_cast<float4*>(optr + 4 * i) = make_float4(a.x, a.y, c.x, c.y);
    }
}

extern "C" void kernel_launch(void* const* d_in, const int* in_sizes, int n_in,
                              void* d_out, int out_size)
{
    const float* x    = (const float*)d_in[0];
    const float* Wk   = (const float*)d_in[1];
    const float* Wq   = (const float*)d_in[2];
    const float* Wv   = (const float*)d_in[3];
    const float* ln1g = (const float*)d_in[4];
    const float* ln1b = (const float*)d_in[5];
    const float* ln2g = (const float*)d_in[6];
    const float* ln2b = (const float*)d_in[7];
    const float* W1   = (const float*)d_in[8];
    const float* b1   = (const float*)d_in[9];
    const float* W2   = (const float*)d_in[10];
    const float* b2   = (const float*)d_in[11];
    float* out = (float*)d_out;

    int B = in_sizes[0] / (TT * DM);
    dim3 grid((B + 1) / 2);
    block_kernel<<<grid, 128>>>(x, Wk, Wq, Wv, ln1g, ln1b, ln2g, ln2b,
                                W1, b1, W2, b2, out);
}

// round 3
// speedup vs baseline: 1.6682x; 1.3458x over previous
#include <cuda_runtime.h>
#include <math.h>

#define TT 64
#define DM 16
#define DFF 32
#define EPSF 1e-5f

typedef unsigned long long u64;

__device__ __forceinline__ u64 pk2(float lo, float hi) {
    u64 r; asm("mov.b64 %0,{%1,%2};" : "=l"(r) : "f"(lo), "f"(hi)); return r;
}
__device__ __forceinline__ float2 up2(u64 v) {
    float2 f; asm("mov.b64 {%0,%1},%2;" : "=f"(f.x), "=f"(f.y) : "l"(v)); return f;
}
__device__ __forceinline__ u64 f2fma(u64 a, u64 b, u64 c) {
    u64 d; asm("fma.rn.f32x2 %0,%1,%2,%3;" : "=l"(d) : "l"(a), "l"(b), "l"(c)); return d;
}
__device__ __forceinline__ u64 f2add(u64 a, u64 b) {
    u64 d; asm("add.rn.f32x2 %0,%1,%2;" : "=l"(d) : "l"(a), "l"(b)); return d;
}
__device__ __forceinline__ u64 f2mul(u64 a, u64 b) {
    u64 d; asm("mul.rn.f32x2 %0,%1,%2;" : "=l"(d) : "l"(a), "l"(b)); return d;
}
__device__ __forceinline__ void ld2(const float* p, u64& a, u64& b) {
    float4 v = *reinterpret_cast<const float4*>(p);
    a = pk2(v.x, v.y); b = pk2(v.z, v.w);
}

// LayerNorm over 16 channels held as 8 packed pairs; writes scalar h[16]
__device__ __forceinline__ void ln16(const u64* xp, const float* g, const float* bb,
                                     float* hs)
{
    u64 acc = f2add(f2add(f2add(xp[0], xp[1]), f2add(xp[2], xp[3])),
                    f2add(f2add(xp[4], xp[5]), f2add(xp[6], xp[7])));
    float2 s2 = up2(acc);
    float mu = (s2.x + s2.y) * (1.0f / DM);
    u64 nmu = pk2(-mu, -mu);
    u64 v0 = 0ull, v1 = 0ull;
    #pragma unroll
    for (int i = 0; i < 8; i += 2) {
        u64 d0 = f2add(xp[i], nmu);     v0 = f2fma(d0, d0, v0);
        u64 d1 = f2add(xp[i + 1], nmu); v1 = f2fma(d1, d1, v1);
    }
    s2 = up2(f2add(v0, v1));
    float rstd = rsqrtf((s2.x + s2.y) * (1.0f / DM) + EPSF);
    u64 rr = pk2(rstd, rstd);
    #pragma unroll
    for (int i = 0; i < 4; i++) {
        u64 ga, gb, ba, b2_;
        ld2(&g[4 * i], ga, gb);
        ld2(&bb[4 * i], ba, b2_);
        u64 h0 = f2fma(f2mul(f2add(xp[2 * i], nmu), rr), ga, ba);
        u64 h1 = f2fma(f2mul(f2add(xp[2 * i + 1], nmu), rr), gb, b2_);
        float2 a = up2(h0), c = up2(h1);
        hs[4 * i] = a.x; hs[4 * i + 1] = a.y; hs[4 * i + 2] = c.x; hs[4 * i + 3] = c.y;
    }
}

// one 16x16 projection for two tokens: acc{A,B}[8] += h{A,B} @ W
__device__ __forceinline__ void proj2(const float (*W)[DM], const float* hA, const float* hB,
                                      u64* aA, u64* aB)
{
    #pragma unroll
    for (int i = 0; i < 8; i++) { aA[i] = 0ull; aB[i] = 0ull; }
    #pragma unroll
    for (int c = 0; c < DM; c++) {
        u64 hbA = pk2(hA[c], hA[c]);
        u64 hbB = pk2(hB[c], hB[c]);
        #pragma unroll
        for (int i = 0; i < 4; i++) {
            u64 wa, wb;
            ld2(&W[c][4 * i], wa, wb);
            aA[2 * i]     = f2fma(hbA, wa, aA[2 * i]);
            aA[2 * i + 1] = f2fma(hbA, wb, aA[2 * i + 1]);
            aB[2 * i]     = f2fma(hbB, wa, aB[2 * i]);
            aB[2 * i + 1] = f2fma(hbB, wb, aB[2 * i + 1]);
        }
    }
}

__device__ __forceinline__ void st_row(float* p, const u64* a)
{
    #pragma unroll
    for (int i = 0; i < 4; i++) {
        float2 lo = up2(a[2 * i]), hi = up2(a[2 * i + 1]);
        *reinterpret_cast<float4*>(p + 4 * i) = make_float4(lo.x, lo.y, hi.x, hi.y);
    }
}

__global__ __launch_bounds__(128, 3)
void block_kernel(const float* __restrict__ x,
                  const float* __restrict__ Wk, const float* __restrict__ Wq,
                  const float* __restrict__ Wv,
                  const float* __restrict__ ln1g, const float* __restrict__ ln1b,
                  const float* __restrict__ ln2g, const float* __restrict__ ln2b,
                  const float* __restrict__ W1, const float* __restrict__ b1,
                  const float* __restrict__ W2, const float* __restrict__ b2,
                  float* __restrict__ out)
{
    __shared__ float sWk[DM][DM], sWq[DM][DM], sWv[DM][DM];
    __shared__ float sW1[DM][DFF], sW2[DFF][DM];
    __shared__ float sb1[DFF], sb2[DM], sg1[DM], sB1[DM], sg2[DM], sB2[DM];
    __shared__ float sK[4][TT][DM], sV[4][TT][DM];

    const int tid = threadIdx.x;
    const int w   = tid >> 5;          // warp = one batch element
    const int t   = tid & 31;          // token A = t, token B = t + 32
    const long long b = (long long)blockIdx.x * 4 + w;

    // ---- cooperative weight load ----
    for (int i = tid; i < DM * DM; i += 128) {
        ((float*)sWk)[i] = Wk[i];
        ((float*)sWq)[i] = Wq[i];
        ((float*)sWv)[i] = Wv[i];
    }
    for (int i = tid; i < DM * DFF; i += 128) {
        ((float*)sW1)[i] = W1[i];
        ((float*)sW2)[i] = W2[i];
    }
    if (tid < DFF) sb1[tid] = b1[tid];
    if (tid < DM) {
        sb2[tid] = b2[tid];
        sg1[tid] = ln1g[tid]; sB1[tid] = ln1b[tid];
        sg2[tid] = ln2g[tid]; sB2[tid] = ln2b[tid];
    }

    // ---- load both token rows ----
    u64 xA[8], xB[8];
    const float* xa = x + (b * TT + t) * DM;
    #pragma unroll
    for (int i = 0; i < 4; i++) {
        float4 v4 = *reinterpret_cast<const float4*>(xa + 4 * i);
        xA[2 * i] = pk2(v4.x, v4.y); xA[2 * i + 1] = pk2(v4.z, v4.w);
        float4 w4 = *reinterpret_cast<const float4*>(xa + 32 * DM + 4 * i);
        xB[2 * i] = pk2(w4.x, w4.y); xB[2 * i + 1] = pk2(w4.z, w4.w);
    }
    __syncthreads();   // weights ready

    // ---- LN1 ----
    float hA[DM], hB[DM];
    ln16(xA, sg1, sB1, hA);
    ln16(xB, sg1, sB1, hB);

    // ---- K, V, Q projections (phased to limit live registers) ----
    {
        u64 aA[8], aB[8];
        proj2(sWk, hA, hB, aA, aB);
        st_row(&sK[w][t][0], aA);
        st_row(&sK[w][t + 32][0], aB);
        proj2(sWv, hA, hB, aA, aB);
        st_row(&sV[w][t][0], aA);
        st_row(&sV[w][t + 32][0], aB);
    }
    u64 qA[8], qB[8];
    proj2(sWq, hA, hB, qA, qB);
    {   // fold 1/sqrt(C) = 0.25 into q
        u64 qt = pk2(0.25f, 0.25f);
        #pragma unroll
        for (int i = 0; i < 8; i++) { qA[i] = f2mul(qA[i], qt); qB[i] = f2mul(qB[i], qt); }
    }
    __syncwarp();      // this warp's K/V tile ready (only this warp reads it)

    // ---- causal attention: single pass, no max subtraction ----
    float lA = 0.f, lB = 0.f;
    u64 yA[8], yB[8];
    #pragma unroll
    for (int i = 0; i < 8; i++) { yA[i] = 0ull; yB[i] = 0ull; }

    const float (*Kw)[DM] = sK[w];
    const float (*Vw)[DM] = sV[w];

    #pragma unroll
    for (int s = 0; s < 32; s++) {          // both tokens attend
        u64 kr[8];
        ld2(&Kw[s][0], kr[0], kr[1]); ld2(&Kw[s][4], kr[2], kr[3]);
        ld2(&Kw[s][8], kr[4], kr[5]); ld2(&Kw[s][12], kr[6], kr[7]);
        u64 a0 = 0ull, a1 = 0ull, b0 = 0ull, b1_ = 0ull;
        #pragma unroll
        for (int i = 0; i < 4; i++) {
            a0  = f2fma(qA[2 * i],     kr[2 * i],     a0);
            a1  = f2fma(qA[2 * i + 1], kr[2 * i + 1], a1);
            b0  = f2fma(qB[2 * i],     kr[2 * i],     b0);
            b1_ = f2fma(qB[2 * i + 1], kr[2 * i + 1], b1_);
        }
        float2 fa = up2(f2add(a0, a1)), fb = up2(f2add(b0, b1_));
        float pA = (s <= t) ? __expf(fa.x + fa.y) : 0.f;
        float pB = __expf(fb.x + fb.y);
        lA += pA; lB += pB;
        u64 vr[8];
        ld2(&Vw[s][0], vr[0], vr[1]); ld2(&Vw[s][4], vr[2], vr[3]);
        ld2(&Vw[s][8], vr[4], vr[5]); ld2(&Vw[s][12], vr[6], vr[7]);
        u64 pAp = pk2(pA, pA), pBp = pk2(pB, pB);
        #pragma unroll
        for (int i = 0; i < 8; i++) {
            yA[i] = f2fma(pAp, vr[i], yA[i]);
            yB[i] = f2fma(pBp, vr[i], yB[i]);
        }
    }
    #pragma unroll
    for (int s = 32; s < TT; s++) {         // only token B attends
        u64 kr[8];
        ld2(&Kw[s][0], kr[0], kr[1]); ld2(&Kw[s][4], kr[2], kr[3]);
        ld2(&Kw[s][8], kr[4], kr[5]); ld2(&Kw[s][12], kr[6], kr[7]);
        u64 b0 = 0ull, b1_ = 0ull;
        #pragma unroll
        for (int i = 0; i < 4; i++) {
            b0  = f2fma(qB[2 * i],     kr[2 * i],     b0);
            b1_ = f2fma(qB[2 * i + 1], kr[2 * i + 1], b1_);
        }
        float2 fb = up2(f2add(b0, b1_));
        float pB = (t >= s - 32) ? __expf(fb.x + fb.y) : 0.f;
        lB += pB;
        u64 vr[8];
        ld2(&Vw[s][0], vr[0], vr[1]); ld2(&Vw[s][4], vr[2], vr[3]);
        ld2(&Vw[s][8], vr[4], vr[5]); ld2(&Vw[s][12], vr[6], vr[7]);
        u64 pBp = pk2(pB, pB);
        #pragma unroll
        for (int i = 0; i < 8; i++) yB[i] = f2fma(pBp, vr[i], yB[i]);
    }

    {   // residual 1
        float invA = __fdividef(1.0f, lA), invB = __fdividef(1.0f, lB);
        u64 ia = pk2(invA, invA), ib = pk2(invB, invB);
        #pragma unroll
        for (int i = 0; i < 8; i++) {
            xA[i] = f2fma(yA[i], ia, xA[i]);
            xB[i] = f2fma(yB[i], ib, xB[i]);
        }
    }

    // ---- LN2 ----
    ln16(xA, sg2, sB2, hA);
    ln16(xB, sg2, sB2, hB);

    // ---- FFN1: f = h2 @ W1 + b1 (both tokens share weight loads) ----
    u64 fA[16], fB[16];
    #pragma unroll
    for (int i = 0; i < 8; i++) {
        u64 ba, bb;
        ld2(&sb1[4 * i], ba, bb);
        fA[2 * i] = ba; fA[2 * i + 1] = bb;
        fB[2 * i] = ba; fB[2 * i + 1] = bb;
    }
    #pragma unroll
    for (int c = 0; c < DM; c++) {
        u64 hbA = pk2(hA[c], hA[c]);
        u64 hbB = pk2(hB[c], hB[c]);
        #pragma unroll
        for (int i = 0; i < 8; i++) {
            u64 wa, wb;
            ld2(&sW1[c][4 * i], wa, wb);
            fA[2 * i]     = f2fma(hbA, wa, fA[2 * i]);
            fA[2 * i + 1] = f2fma(hbA, wb, fA[2 * i + 1]);
            fB[2 * i]     = f2fma(hbB, wa, fB[2 * i]);
            fB[2 * i + 1] = f2fma(hbB, wb, fB[2 * i + 1]);
        }
    }
    // exact GELU, repacked in place
    float fsA[DFF], fsB[DFF];
    #pragma unroll
    for (int i = 0; i < 16; i++) {
        float2 fa = up2(fA[i]), fb = up2(fB[i]);
        fsA[2 * i]     = 0.5f * fa.x * (1.0f + erff(fa.x * 0.70710678118654752f));
        fsA[2 * i + 1] = 0.5f * fa.y * (1.0f + erff(fa.y * 0.70710678118654752f));
        fsB[2 * i]     = 0.5f * fb.x * (1.0f + erff(fb.x * 0.70710678118654752f));
        fsB[2 * i + 1] = 0.5f * fb.y * (1.0f + erff(fb.y * 0.70710678118654752f));
    }

    // ---- FFN2 + residual (shared weight loads) ----
    u64 oA[8], oB[8];
    #pragma unroll
    for (int i = 0; i < 4; i++) {
        u64 ba, bb;
        ld2(&sb2[4 * i], ba, bb);
        oA[2 * i]     = f2add(xA[2 * i], ba);
        oA[2 * i + 1] = f2add(xA[2 * i + 1], bb);
        oB[2 * i]     = f2add(xB[2 * i], ba);
        oB[2 * i + 1] = f2add(xB[2 * i + 1], bb);
    }
    #pragma unroll
    for (int j = 0; j < DFF; j++) {
        u64 fbA = pk2(fsA[j], fsA[j]);
        u64 fbB = pk2(fsB[j], fsB[j]);
        #pragma unroll
        for (int i = 0; i < 4; i++) {
            u64 wa, wb;
            ld2(&sW2[j][4 * i], wa, wb);
            oA[2 * i]     = f2fma(fbA, wa, oA[2 * i]);
            oA[2 * i + 1] = f2fma(fbA, wb, oA[2 * i + 1]);
            oB[2 * i]     = f2fma(fbB, wa, oB[2 * i]);
            oB[2 * i + 1] = f2fma(fbB, wb, oB[2 * i + 1]);
        }
    }

    // ---- store both tokens ----
    float* op = out + (b * TT + t) * DM;
    st_row(op, oA);
    st_row(op + 32 * DM, oB);
}

extern "C" void kernel_launch(void* const* d_in, const int* in_sizes, int n_in,
                              void* d_out, int out_size)
{
    const float* x    = (const float*)d_in[0];
    const float* Wk   = (const float*)d_in[1];
    const float* Wq   = (const float*)d_in[2];
    const float* Wv   = (const float*)d_in[3];
    const float* ln1g = (const float*)d_in[4];
    const float* ln1b = (const float*)d_in[5];
    const float* ln2g = (const float*)d_in[6];
    const float* ln2b = (const float*)d_in[7];
    const float* W1   = (const float*)d_in[8];
    const float* b1   = (const float*)d_in[9];
    const float* W2   = (const float*)d_in[10];
    const float* b2   = (const float*)d_in[11];
    float* out = (float*)d_out;

    int B = in_sizes[0] / (TT * DM);
    dim3 grid((B + 3) / 4);               // 4 batch elements per CTA (1 per warp)
    block_kernel<<<grid, 128>>>(x, Wk, Wq, Wv, ln1g, ln1b, ln2g, ln2b,
                                W1, b1, W2, b2, out);
}